// round 13
// baseline (speedup 1.0000x reference)
#include <cuda_runtime.h>
#include <cuda_fp16.h>
#include <math.h>

#define N_NODES 80000
#define E_EDGES 1280000
#define EP_EDGES (E_EDGES + N_NODES)   /* 1,360,000 with self-loops */
#define C 128
#define NHEAD 8
#define NODE_PER_G 10000
#define BATCH 8
#define EB ((EP_EDGES + 255) / 256)    /* 5313 */
#define ATTB 2500                       /* N*8/256 */
#define SLOT 64                         /* max degree bucket (P(deg>63)~1e-17) */

// ---------------- device scratch ----------------
__device__ __half g_h[N_NODES * C];
__device__ __half g_acc[N_NODES * C];
__device__ float g_adst[N_NODES * NHEAD];
__device__ float2 g_srw[N_NODES * NHEAD];   // .x = asrc dot, .y = 1/(sum exp + 1e-16)
__device__ int g_cntS[N_NODES];
__device__ int g_cntD[N_NODES];
__device__ int g_slotS[N_NODES * SLOT];  // dst ids grouped by src
__device__ int g_slotD[N_NODES * SLOT];  // src ids grouped by dst
__device__ float g_bnsum[C], g_bnsq[C];
__device__ float g_pool[BATCH * C];

__device__ __forceinline__ float lrelu(float a) { return a >= 0.f ? a : 0.2f * a; }
__device__ __forceinline__ unsigned h2_to_u(__half2 h) {
    union { __half2 h; unsigned u; } cv; cv.h = h; return cv.u;
}
// ---- packed f32x2 helpers (sm_103a FFMA2 path) ----
__device__ __forceinline__ unsigned long long pack2(float lo, float hi) {
    unsigned long long r;
    asm("mov.b64 %0, {%1, %2};" : "=l"(r) : "r"(__float_as_uint(lo)), "r"(__float_as_uint(hi)));
    return r;
}
__device__ __forceinline__ void unpack2(unsigned long long v, float& lo, float& hi) {
    unsigned a, b;
    asm("mov.b64 {%0, %1}, %2;" : "=r"(a), "=r"(b) : "l"(v));
    lo = __uint_as_float(a); hi = __uint_as_float(b);
}
__device__ __forceinline__ void ffma2(unsigned long long& acc, unsigned long long v, unsigned long long w) {
    asm("fma.rn.f32x2 %0, %1, %2, %0;" : "+l"(acc) : "l"(v), "l"(w));
}
__device__ __forceinline__ void acc8(unsigned long long* a, uint4 p, unsigned long long w2) {
    union { unsigned u; __half2 h; } c0, c1, c2, c3;
    c0.u = p.x; c1.u = p.y; c2.u = p.z; c3.u = p.w;
    float2 f0 = __half22float2(c0.h), f1 = __half22float2(c1.h);
    float2 f2 = __half22float2(c2.h), f3 = __half22float2(c3.h);
    ffma2(a[0], pack2(f0.x, f0.y), w2);
    ffma2(a[1], pack2(f1.x, f1.y), w2);
    ffma2(a[2], pack2(f2.x, f2.y), w2);
    ffma2(a[3], pack2(f3.x, f3.y), w2);
}

// ============ kernel 1: bump-bucket CSR build (both dirs) + layer-1 GEMM + folded att dots ============
__global__ void k_build_gemm(const int* __restrict__ ei, const float* __restrict__ xin,
                             const float* __restrict__ W1, const float* __restrict__ att) {
    int b = blockIdx.x, t = threadIdx.x;
    if (b < EB) {
        int e = b * 256 + t;
        if (e < EP_EDGES) {
            int s, d;
            if (e < E_EDGES) { s = ei[e]; d = ei[E_EDGES + e]; } else { s = d = e - E_EDGES; }
            int ps = atomicAdd(&g_cntS[s], 1);
            g_slotS[s * SLOT + ps] = d;
            int pd = atomicAdd(&g_cntD[d], 1);
            g_slotD[d * SLOT + pd] = s;
        }
    } else if (b < EB + 40000) {
        // pure layer-1 GEMM (in_dim=8)
        int id = (b - EB) * 256 + t;
        int n = id >> 7, o = id & 127;
        const float* xr = xin + n * 8;
        const float* wr = W1 + o * 8;
        float a = 0.f;
#pragma unroll
        for (int k = 0; k < 8; k++) a += xr[k] * wr[k];
        g_h[id] = __float2half_rn(a);
    } else {
        // attention dots via A folded through W1
        __shared__ float FD[64], FS[64];
        if (t < 64) {
            int h = t >> 3, k = t & 7;
            float fd = 0.f, fs = 0.f;
#pragma unroll
            for (int c = 0; c < 16; c++) {
                float w = W1[(h * 16 + c) * 8 + k];
                fd += w * att[h * 32 + c];
                fs += w * att[h * 32 + 16 + c];
            }
            FD[t] = fd; FS[t] = fs;
        }
        __syncthreads();
        int id = (b - EB - 40000) * 256 + t;   // 2500 blocks -> N*8 threads
        int n = id >> 3, h = id & 7;
        const float* xr = xin + n * 8;
        const float* fd = FD + h * 8;
        const float* fs = FS + h * 8;
        float pd = 0.f, ps = 0.f;
#pragma unroll
        for (int k = 0; k < 8; k++) {
            float xv = xr[k];
            pd += xv * fd[k];
            ps += xv * fs[k];
        }
        g_adst[id] = pd;
        g_srw[id].x = ps;
    }
}

// ============ src-grouped softmax denominators + BN-stat zeroing ============
__global__ void k_srcsoft() {
    if (blockIdx.x == 0 && threadIdx.x < 128) {   // zero BN stats for the gather that follows
        g_bnsum[threadIdx.x] = 0.f;
        g_bnsq[threadIdx.x] = 0.f;
    }
    int id = blockIdx.x * 256 + threadIdx.x;   // 2500 blocks, thread = (src, head)
    int s = id >> 3, h = id & 7;
    float as = g_srw[id].x;
    int i = s * SLOT;
    int end = i + g_cntS[s];
    float den = 0.f;
    for (; i + 2 <= end; i += 2) {
        int d0 = g_slotS[i], d1 = g_slotS[i + 1];
        den += __expf(lrelu(g_adst[d0 * 8 + h] + as)) + __expf(lrelu(g_adst[d1 * 8 + h] + as));
    }
    if (i < end) {
        int d = g_slotS[i];
        den += __expf(lrelu(g_adst[d * 8 + h] + as));
    }
    g_srw[id].y = 1.f / (den + 1e-16f);
}

// ============ gather: 8 lanes per dst (lane == head), FFMA2, fused BN stats, unroll 4 ============
__global__ void __launch_bounds__(256) k_gather(const float* __restrict__ bias) {
    __shared__ float bns[128], bnq[128];
    int t = threadIdx.x;
    if (t < 128) { bns[t] = 0.f; bnq[t] = 0.f; }
    __syncthreads();
    int warp = t >> 5, l = t & 31;
    int g = l >> 3;          // node group within warp (0..3)
    int gl = l & 7;          // lane within group == head index
    int d = blockIdx.x * 32 + warp * 4 + g;   // grid 2500 -> 32 nodes/block
    float adh = g_adst[d * 8 + gl];
    int i = d * SLOT;
    int end = i + g_cntD[d];
    unsigned long long acc[8];
#pragma unroll
    for (int j = 0; j < 8; j++) acc[j] = 0ULL;
    const __half* hrow = g_h;
    for (; i + 4 <= end; i += 4) {
        int s0 = g_slotD[i], s1 = g_slotD[i + 1];
        int s2 = g_slotD[i + 2], s3 = g_slotD[i + 3];
        float2 sw0 = g_srw[s0 * 8 + gl];
        float2 sw1 = g_srw[s1 * 8 + gl];
        float2 sw2 = g_srw[s2 * 8 + gl];
        float2 sw3 = g_srw[s3 * 8 + gl];
        const uint4* r0 = (const uint4*)(hrow + s0 * 128 + gl * 16);
        const uint4* r1 = (const uint4*)(hrow + s1 * 128 + gl * 16);
        const uint4* r2 = (const uint4*)(hrow + s2 * 128 + gl * 16);
        const uint4* r3 = (const uint4*)(hrow + s3 * 128 + gl * 16);
        uint4 p0 = r0[0], q0 = r0[1];
        uint4 p1 = r1[0], q1 = r1[1];
        uint4 p2 = r2[0], q2 = r2[1];
        uint4 p3 = r3[0], q3 = r3[1];
        float w0 = __expf(lrelu(adh + sw0.x)) * sw0.y;
        float w1 = __expf(lrelu(adh + sw1.x)) * sw1.y;
        float w2 = __expf(lrelu(adh + sw2.x)) * sw2.y;
        float w3 = __expf(lrelu(adh + sw3.x)) * sw3.y;
        unsigned long long w20 = pack2(w0, w0), w21 = pack2(w1, w1);
        unsigned long long w22 = pack2(w2, w2), w23 = pack2(w3, w3);
        acc8(acc, p0, w20); acc8(acc + 4, q0, w20);
        acc8(acc, p1, w21); acc8(acc + 4, q1, w21);
        acc8(acc, p2, w22); acc8(acc + 4, q2, w22);
        acc8(acc, p3, w23); acc8(acc + 4, q3, w23);
    }
    for (; i < end; i++) {
        int s = g_slotD[i];
        float2 sw = g_srw[s * 8 + gl];
        float w = __expf(lrelu(adh + sw.x)) * sw.y;
        const uint4* r = (const uint4*)(hrow + s * 128 + gl * 16);
        uint4 p = r[0], q = r[1];
        unsigned long long w2 = pack2(w, w);
        acc8(acc, p, w2); acc8(acc + 4, q, w2);
    }
    // epilogue: bias + relu, fp16 store, BN partial sums
    float rv[16];
#pragma unroll
    for (int j = 0; j < 8; j++) unpack2(acc[j], rv[2 * j], rv[2 * j + 1]);
    const float4* bp = (const float4*)(bias + gl * 16);
#pragma unroll
    for (int j = 0; j < 4; j++) {
        float4 b4 = bp[j];
        rv[4 * j + 0] = fmaxf(rv[4 * j + 0] + b4.x, 0.f);
        rv[4 * j + 1] = fmaxf(rv[4 * j + 1] + b4.y, 0.f);
        rv[4 * j + 2] = fmaxf(rv[4 * j + 2] + b4.z, 0.f);
        rv[4 * j + 3] = fmaxf(rv[4 * j + 3] + b4.w, 0.f);
    }
    uint4 o0, o1;
    o0.x = h2_to_u(__floats2half2_rn(rv[0], rv[1]));
    o0.y = h2_to_u(__floats2half2_rn(rv[2], rv[3]));
    o0.z = h2_to_u(__floats2half2_rn(rv[4], rv[5]));
    o0.w = h2_to_u(__floats2half2_rn(rv[6], rv[7]));
    o1.x = h2_to_u(__floats2half2_rn(rv[8], rv[9]));
    o1.y = h2_to_u(__floats2half2_rn(rv[10], rv[11]));
    o1.z = h2_to_u(__floats2half2_rn(rv[12], rv[13]));
    o1.w = h2_to_u(__floats2half2_rn(rv[14], rv[15]));
    uint4* op = (uint4*)(g_acc + d * 128 + gl * 16);
    op[0] = o0; op[1] = o1;
    // BN: reduce across the 4 node groups, stage in smem
#pragma unroll
    for (int j = 0; j < 16; j++) {
        float v = rv[j];
        float q = v * v;
        v += __shfl_xor_sync(0xffffffffu, v, 8);
        v += __shfl_xor_sync(0xffffffffu, v, 16);
        q += __shfl_xor_sync(0xffffffffu, q, 8);
        q += __shfl_xor_sync(0xffffffffu, q, 16);
        if (l < 8) {
            atomicAdd(&bns[gl * 16 + j], v);
            atomicAdd(&bnq[gl * 16 + j], q);
        }
    }
    __syncthreads();
    if (t < 128) {
        atomicAdd(&g_bnsum[t], bns[t]);
        atomicAdd(&g_bnsq[t], bnq[t]);
    }
}

// ============ 128x128 GEMM: 256 threads, 8x8 blocking, FFMA2 packed accumulators ============
__global__ void __launch_bounds__(256) k_gemm128(const float* __restrict__ W,
                                                 const float* __restrict__ att,
                                                 const float* __restrict__ gam,
                                                 const float* __restrict__ bet) {
    __shared__ float Xs[128][33];    // [node][kk] — staging writes conflict-free
    __shared__ float Ws[32][136];    // [kk][orow] — float2/float4 reads
    __shared__ float A[256];
    __shared__ float Ss[128], Hs[128];
    int t = threadIdx.x;
    int lane = t & 31;
    int row8 = t >> 5;      // 0..7
    int og = t & 15;        // outputs og*8..+8
    int ng = t >> 4;        // 0..15 -> nodes ng*8..+8
    int o0 = og * 8;
    int n0 = blockIdx.x * 128;

    A[t] = att[t];
    if (t < 128) {
        float m = g_bnsum[t] * (1.f / (float)N_NODES);
        float var = g_bnsq[t] * (1.f / (float)N_NODES) - m * m;
        float sc = gam[t] * rsqrtf(var + 1e-5f);
        Ss[t] = sc;
        Hs[t] = bet[t] - m * sc;
    }
    __syncthreads();

    // packed accumulators: acc2[i][j] = (out 2j, out 2j+1) for node i
    unsigned long long acc2[8][4];
#pragma unroll
    for (int i = 0; i < 8; i++)
#pragma unroll
        for (int j = 0; j < 4; j++) acc2[i][j] = 0ULL;

    for (int kt = 0; kt < 128; kt += 32) {
        float sc = Ss[kt + lane], sh = Hs[kt + lane];
        // stage X: Xs[r][lane] (conflict-free: stride 33)
#pragma unroll
        for (int p = 0; p < 16; p++) {
            int r = row8 + p * 8;   // 0..127
            float v = __half2float(g_acc[(n0 + r) * 128 + kt + lane]);
            float y = v * sc + sh;
            Xs[r][lane] = (y >= 0.f) ? y : 0.2f * y;
        }
        // stage W transposed: Ws[kk][orow]
#pragma unroll
        for (int p = 0; p < 16; p++) {
            int orow = row8 + p * 8;   // 0..127
            Ws[lane][orow] = W[orow * 128 + kt + lane];
        }
        __syncthreads();
#pragma unroll 4
        for (int kk = 0; kk < 32; kk++) {
            float2 w01 = *(const float2*)&Ws[kk][o0];
            float2 w23 = *(const float2*)&Ws[kk][o0 + 2];
            float2 w45 = *(const float2*)&Ws[kk][o0 + 4];
            float2 w67 = *(const float2*)&Ws[kk][o0 + 6];
            unsigned long long W01 = pack2(w01.x, w01.y);
            unsigned long long W23 = pack2(w23.x, w23.y);
            unsigned long long W45 = pack2(w45.x, w45.y);
            unsigned long long W67 = pack2(w67.x, w67.y);
#pragma unroll
            for (int i = 0; i < 8; i++) {
                float xv = Xs[ng * 8 + i][kk];
                unsigned long long xx = pack2(xv, xv);
                ffma2(acc2[i][0], xx, W01);
                ffma2(acc2[i][1], xx, W23);
                ffma2(acc2[i][2], xx, W45);
                ffma2(acc2[i][3], xx, W67);
            }
        }
        __syncthreads();
    }
    int head = og >> 1;
    int c0 = (og & 1) * 8;
#pragma unroll
    for (int i = 0; i < 8; i++) {
        int n = n0 + ng * 8 + i;
        float v[8];
#pragma unroll
        for (int j = 0; j < 4; j++) unpack2(acc2[i][j], v[2 * j], v[2 * j + 1]);
        uint4 pack;
        pack.x = h2_to_u(__floats2half2_rn(v[0], v[1]));
        pack.y = h2_to_u(__floats2half2_rn(v[2], v[3]));
        pack.z = h2_to_u(__floats2half2_rn(v[4], v[5]));
        pack.w = h2_to_u(__floats2half2_rn(v[6], v[7]));
        *(uint4*)(g_h + n * 128 + o0) = pack;
        float pd = 0.f, ps = 0.f;
#pragma unroll
        for (int q = 0; q < 8; q++) {
            pd += v[q] * A[head * 32 + c0 + q];
            ps += v[q] * A[head * 32 + 16 + c0 + q];
        }
        pd += __shfl_xor_sync(0xffffffffu, pd, 1);
        ps += __shfl_xor_sync(0xffffffffu, ps, 1);
        if (!(og & 1)) { g_adst[n * 8 + head] = pd; g_srw[n * 8 + head].x = ps; }
    }
}

// ============ power-mean pooling (BN affine inline) + head + CSR counter re-zero ============
__global__ void k_poolsum(const float* __restrict__ pp, const float* __restrict__ gam,
                          const float* __restrict__ bet) {
    float p = pp[0];
    int b = blockIdx.y, chunk = blockIdx.x, c = threadIdx.x;  // 128 threads
    float m = g_bnsum[c] * (1.f / (float)N_NODES);
    float var = g_bnsq[c] * (1.f / (float)N_NODES) - m * m;
    float sc = gam[c] * rsqrtf(var + 1e-5f);
    float sh = bet[c] - m * sc;
    float s = 0.f;
    int i0 = chunk * 313;
    int iend = min(i0 + 313, NODE_PER_G);
    for (int i = i0; i < iend; i++) {
        float v = __half2float(g_acc[(b * NODE_PER_G + i) * 128 + c]);
        float y = v * sc + sh;
        y = (y >= 0.f) ? y : 0.2f * y;
        y = fminf(fmaxf(y, 0.f), 100.f);
        if (p != 1.f) y = (y > 0.f) ? __powf(y, p) : 0.f;
        s += y;
    }
    atomicAdd(&g_pool[b * 128 + c], s);
    // re-zero bump-CSR counters for the next graph replay
    int tid = (b * 32 + chunk) * 128 + c;
    for (int idx = tid; idx < N_NODES; idx += 32 * BATCH * 128) {
        g_cntS[idx] = 0;
        g_cntD[idx] = 0;
    }
}
__global__ void k_final(float* out, int out_size, const float* __restrict__ pp,
                        const float* __restrict__ Wg, const float* __restrict__ bg) {
    __shared__ float xg[1024];
    __shared__ float lg[16];
    int t = threadIdx.x;   // 1024
    float p = pp[0];
    {
        float m = g_pool[t] * (1.f / (float)NODE_PER_G);
        g_pool[t] = 0.f;
        if (t < 128) { g_bnsum[t] = 0.f; g_bnsq[t] = 0.f; }
        m = fminf(fmaxf(m, 0.f), 100.f);
        if (p != 1.f) m = (m > 0.f) ? __powf(m, 1.f / p) : 0.f;
        xg[t] = m;
    }
    __syncthreads();
    if (t < 16) {
        int b = t >> 1, cls = t & 1;
        float a = bg[cls];
        const float* w = Wg + cls * 128;
        const float* xr = xg + b * 128;
        for (int c2 = 0; c2 < 128; c2++) a += xr[c2] * w[c2];
        lg[t] = a;
        if (t < out_size) out[t] = a;
    }
    __syncthreads();
    if (t < 8 && (16 + t) < out_size) {
        out[16 + t] = (lg[2 * t + 1] > lg[2 * t]) ? 1.f : 0.f;
    }
}

// ============================ host driver (11 launches) ============================
extern "C" void kernel_launch(void* const* d_in, const int* in_sizes, int n_in,
                              void* d_out, int out_size) {
    const float* x    = (const float*)d_in[0];
    const int*   ei   = (const int*)d_in[1];
    const float* W1   = (const float*)d_in[2];
    const float* att1 = (const float*)d_in[3];
    const float* b1   = (const float*)d_in[4];
    const float* g1   = (const float*)d_in[5];
    const float* be1  = (const float*)d_in[6];
    const float* W2   = (const float*)d_in[7];
    const float* att2 = (const float*)d_in[8];
    const float* b2   = (const float*)d_in[9];
    const float* g2   = (const float*)d_in[10];
    const float* be2  = (const float*)d_in[11];
    const float* W3   = (const float*)d_in[12];
    const float* att3 = (const float*)d_in[13];
    const float* b3   = (const float*)d_in[14];
    const float* g3   = (const float*)d_in[15];
    const float* be3  = (const float*)d_in[16];
    const float* p    = (const float*)d_in[17];
    const float* Wg   = (const float*)d_in[18];
    const float* bg   = (const float*)d_in[19];
    float* out = (float*)d_out;

    // 1: bump-bucket CSR (both dirs) + layer-1 GEMM + folded att dots
    k_build_gemm<<<EB + 40000 + ATTB, 256>>>(ei, x, W1, att1);
    // layer 1
    k_srcsoft<<<2500, 256>>>();
    k_gather<<<2500, 256>>>(b1);
    // layer 2
    k_gemm128<<<N_NODES / 128, 256>>>(W2, att2, g1, be1);   // <- profiled slot
    k_srcsoft<<<2500, 256>>>();
    k_gather<<<2500, 256>>>(b2);
    // layer 3
    k_gemm128<<<N_NODES / 128, 256>>>(W3, att3, g2, be2);
    k_srcsoft<<<2500, 256>>>();
    k_gather<<<2500, 256>>>(b3);
    // pooling + head (+ CSR counter re-zero)
    k_poolsum<<<dim3(32, BATCH), 128>>>(p, g3, be3);
    k_final<<<1, 1024>>>(out, out_size, p, Wg, bg);
}

// round 14
// speedup vs baseline: 1.0989x; 1.0989x over previous
#include <cuda_runtime.h>
#include <cuda_fp16.h>
#include <math.h>

#define N_NODES 80000
#define E_EDGES 1280000
#define EP_EDGES (E_EDGES + N_NODES)   /* 1,360,000 with self-loops */
#define C 128
#define NHEAD 8
#define NODE_PER_G 10000
#define BATCH 8
#define EB ((EP_EDGES + 255) / 256)    /* 5313 */
#define GB1 2500                        /* N*8/256 layer-1 blocks (thread = node,head) */
#define SLOT 64                         /* max degree bucket (P(deg>63)~1e-17) */

// ---------------- device scratch ----------------
__device__ __half g_h[N_NODES * C];
__device__ __half g_acc[N_NODES * C];
__device__ float g_adst[N_NODES * NHEAD];
__device__ float2 g_srw[N_NODES * NHEAD];   // .x = asrc dot, .y = 1/(sum exp + 1e-16)
__device__ int g_cntS[N_NODES];
__device__ int g_cntD[N_NODES];
__device__ int g_slotS[N_NODES * SLOT];  // dst ids grouped by src
__device__ int g_slotD[N_NODES * SLOT];  // src ids grouped by dst
__device__ float g_bnsum[C], g_bnsq[C];
__device__ float g_pool[BATCH * C];

__device__ __forceinline__ float lrelu(float a) { return a >= 0.f ? a : 0.2f * a; }
__device__ __forceinline__ unsigned h2_to_u(__half2 h) {
    union { __half2 h; unsigned u; } cv; cv.h = h; return cv.u;
}
// ---- packed f32x2 helpers (sm_103a FFMA2 path) ----
__device__ __forceinline__ unsigned long long pack2(float lo, float hi) {
    unsigned long long r;
    asm("mov.b64 %0, {%1, %2};" : "=l"(r) : "r"(__float_as_uint(lo)), "r"(__float_as_uint(hi)));
    return r;
}
__device__ __forceinline__ void unpack2(unsigned long long v, float& lo, float& hi) {
    unsigned a, b;
    asm("mov.b64 {%0, %1}, %2;" : "=r"(a), "=r"(b) : "l"(v));
    lo = __uint_as_float(a); hi = __uint_as_float(b);
}
__device__ __forceinline__ void ffma2(unsigned long long& acc, unsigned long long v, unsigned long long w) {
    asm("fma.rn.f32x2 %0, %1, %2, %0;" : "+l"(acc) : "l"(v), "l"(w));
}
__device__ __forceinline__ void acc8(unsigned long long* a, uint4 p, unsigned long long w2) {
    union { unsigned u; __half2 h; } c0, c1, c2, c3;
    c0.u = p.x; c1.u = p.y; c2.u = p.z; c3.u = p.w;
    float2 f0 = __half22float2(c0.h), f1 = __half22float2(c1.h);
    float2 f2 = __half22float2(c2.h), f3 = __half22float2(c3.h);
    ffma2(a[0], pack2(f0.x, f0.y), w2);
    ffma2(a[1], pack2(f1.x, f1.y), w2);
    ffma2(a[2], pack2(f2.x, f2.y), w2);
    ffma2(a[3], pack2(f3.x, f3.y), w2);
}

// ============ kernel 1: bump-bucket CSR build + layer-1 GEMM (thread = node,head) + att dots ============
__global__ void k_build_gemm(const int* __restrict__ ei, const float* __restrict__ xin,
                             const float* __restrict__ W1, const float* __restrict__ att) {
    int b = blockIdx.x, t = threadIdx.x;
    if (b < EB) {
        int e = b * 256 + t;
        if (e < EP_EDGES) {
            int s, d;
            if (e < E_EDGES) { s = ei[e]; d = ei[E_EDGES + e]; } else { s = d = e - E_EDGES; }
            int ps = atomicAdd(&g_cntS[s], 1);
            g_slotS[s * SLOT + ps] = d;
            int pd = atomicAdd(&g_cntD[d], 1);
            g_slotD[d * SLOT + pd] = s;
        }
    } else {
        // layer-1 GEMM: one thread per (node, head). W1 in smem, head-stride 132 (conflict-free).
        __shared__ float W1p[8 * 132];   // W1p[h*132 + k*16 + c] = W1[(h*16+c)*8 + k]
        __shared__ float As[256];
        As[t] = att[t];
        for (int idx = t; idx < 1024; idx += 256) {
            int o = idx >> 3, k = idx & 7;
            int h = o >> 4, c = o & 15;
            W1p[h * 132 + k * 16 + c] = W1[idx];
        }
        __syncthreads();
        int id = (b - EB) * 256 + t;   // GB1 blocks -> N*8 threads
        int n = id >> 3, h = id & 7;
        float4 x0 = *(const float4*)(xin + n * 8);
        float4 x1 = *(const float4*)(xin + n * 8 + 4);
        float xk[8] = {x0.x, x0.y, x0.z, x0.w, x1.x, x1.y, x1.z, x1.w};
        float v[16];
#pragma unroll
        for (int c = 0; c < 16; c++) v[c] = 0.f;
        const float* wp = W1p + h * 132;
#pragma unroll
        for (int k = 0; k < 8; k++) {
            float xv = xk[k];
            float4 wa = *(const float4*)(wp + k * 16);
            float4 wb = *(const float4*)(wp + k * 16 + 4);
            float4 wc = *(const float4*)(wp + k * 16 + 8);
            float4 wd = *(const float4*)(wp + k * 16 + 12);
            v[0] += xv * wa.x; v[1] += xv * wa.y; v[2] += xv * wa.z; v[3] += xv * wa.w;
            v[4] += xv * wb.x; v[5] += xv * wb.y; v[6] += xv * wb.z; v[7] += xv * wb.w;
            v[8] += xv * wc.x; v[9] += xv * wc.y; v[10] += xv * wc.z; v[11] += xv * wc.w;
            v[12] += xv * wd.x; v[13] += xv * wd.y; v[14] += xv * wd.z; v[15] += xv * wd.w;
        }
        // fp16 store (32B contiguous per thread, 1KB linear per warp)
        uint4 p0, p1;
        p0.x = h2_to_u(__floats2half2_rn(v[0], v[1]));
        p0.y = h2_to_u(__floats2half2_rn(v[2], v[3]));
        p0.z = h2_to_u(__floats2half2_rn(v[4], v[5]));
        p0.w = h2_to_u(__floats2half2_rn(v[6], v[7]));
        p1.x = h2_to_u(__floats2half2_rn(v[8], v[9]));
        p1.y = h2_to_u(__floats2half2_rn(v[10], v[11]));
        p1.z = h2_to_u(__floats2half2_rn(v[12], v[13]));
        p1.w = h2_to_u(__floats2half2_rn(v[14], v[15]));
        uint4* hp = (uint4*)(g_h + n * 128 + h * 16);
        hp[0] = p0; hp[1] = p1;
        // attention dots: full head in-thread, no shuffles
        float pd = 0.f, ps = 0.f;
        const float* a1 = As + h * 32;
#pragma unroll
        for (int c = 0; c < 16; c++) {
            pd += v[c] * a1[c];
            ps += v[c] * a1[16 + c];
        }
        g_adst[id] = pd;
        g_srw[id].x = ps;
    }
}

// ============ src-grouped softmax denominators + BN-stat zeroing ============
__global__ void k_srcsoft() {
    if (blockIdx.x == 0 && threadIdx.x < 128) {   // zero BN stats for the gather that follows
        g_bnsum[threadIdx.x] = 0.f;
        g_bnsq[threadIdx.x] = 0.f;
    }
    int id = blockIdx.x * 256 + threadIdx.x;   // 2500 blocks, thread = (src, head)
    int s = id >> 3, h = id & 7;
    float as = g_srw[id].x;
    int i = s * SLOT;
    int end = i + g_cntS[s];
    float den = 0.f;
    for (; i + 2 <= end; i += 2) {
        int d0 = g_slotS[i], d1 = g_slotS[i + 1];
        den += __expf(lrelu(g_adst[d0 * 8 + h] + as)) + __expf(lrelu(g_adst[d1 * 8 + h] + as));
    }
    if (i < end) {
        int d = g_slotS[i];
        den += __expf(lrelu(g_adst[d * 8 + h] + as));
    }
    g_srw[id].y = 1.f / (den + 1e-16f);
}

// ============ gather: 8 lanes per dst (lane == head), FFMA2, fused BN stats, unroll 4 ============
__global__ void __launch_bounds__(256) k_gather(const float* __restrict__ bias) {
    __shared__ float bns[128], bnq[128];
    int t = threadIdx.x;
    if (t < 128) { bns[t] = 0.f; bnq[t] = 0.f; }
    __syncthreads();
    int warp = t >> 5, l = t & 31;
    int g = l >> 3;          // node group within warp (0..3)
    int gl = l & 7;          // lane within group == head index
    int d = blockIdx.x * 32 + warp * 4 + g;   // grid 2500 -> 32 nodes/block
    float adh = g_adst[d * 8 + gl];
    int i = d * SLOT;
    int end = i + g_cntD[d];
    unsigned long long acc[8];
#pragma unroll
    for (int j = 0; j < 8; j++) acc[j] = 0ULL;
    const __half* hrow = g_h;
    for (; i + 4 <= end; i += 4) {
        int s0 = g_slotD[i], s1 = g_slotD[i + 1];
        int s2 = g_slotD[i + 2], s3 = g_slotD[i + 3];
        float2 sw0 = g_srw[s0 * 8 + gl];
        float2 sw1 = g_srw[s1 * 8 + gl];
        float2 sw2 = g_srw[s2 * 8 + gl];
        float2 sw3 = g_srw[s3 * 8 + gl];
        const uint4* r0 = (const uint4*)(hrow + s0 * 128 + gl * 16);
        const uint4* r1 = (const uint4*)(hrow + s1 * 128 + gl * 16);
        const uint4* r2 = (const uint4*)(hrow + s2 * 128 + gl * 16);
        const uint4* r3 = (const uint4*)(hrow + s3 * 128 + gl * 16);
        uint4 p0 = r0[0], q0 = r0[1];
        uint4 p1 = r1[0], q1 = r1[1];
        uint4 p2 = r2[0], q2 = r2[1];
        uint4 p3 = r3[0], q3 = r3[1];
        float w0 = __expf(lrelu(adh + sw0.x)) * sw0.y;
        float w1 = __expf(lrelu(adh + sw1.x)) * sw1.y;
        float w2 = __expf(lrelu(adh + sw2.x)) * sw2.y;
        float w3 = __expf(lrelu(adh + sw3.x)) * sw3.y;
        unsigned long long w20 = pack2(w0, w0), w21 = pack2(w1, w1);
        unsigned long long w22 = pack2(w2, w2), w23 = pack2(w3, w3);
        acc8(acc, p0, w20); acc8(acc + 4, q0, w20);
        acc8(acc, p1, w21); acc8(acc + 4, q1, w21);
        acc8(acc, p2, w22); acc8(acc + 4, q2, w22);
        acc8(acc, p3, w23); acc8(acc + 4, q3, w23);
    }
    for (; i < end; i++) {
        int s = g_slotD[i];
        float2 sw = g_srw[s * 8 + gl];
        float w = __expf(lrelu(adh + sw.x)) * sw.y;
        const uint4* r = (const uint4*)(hrow + s * 128 + gl * 16);
        uint4 p = r[0], q = r[1];
        unsigned long long w2 = pack2(w, w);
        acc8(acc, p, w2); acc8(acc + 4, q, w2);
    }
    // epilogue: bias + relu, fp16 store, BN partial sums
    float rv[16];
#pragma unroll
    for (int j = 0; j < 8; j++) unpack2(acc[j], rv[2 * j], rv[2 * j + 1]);
    const float4* bp = (const float4*)(bias + gl * 16);
#pragma unroll
    for (int j = 0; j < 4; j++) {
        float4 b4 = bp[j];
        rv[4 * j + 0] = fmaxf(rv[4 * j + 0] + b4.x, 0.f);
        rv[4 * j + 1] = fmaxf(rv[4 * j + 1] + b4.y, 0.f);
        rv[4 * j + 2] = fmaxf(rv[4 * j + 2] + b4.z, 0.f);
        rv[4 * j + 3] = fmaxf(rv[4 * j + 3] + b4.w, 0.f);
    }
    uint4 o0, o1;
    o0.x = h2_to_u(__floats2half2_rn(rv[0], rv[1]));
    o0.y = h2_to_u(__floats2half2_rn(rv[2], rv[3]));
    o0.z = h2_to_u(__floats2half2_rn(rv[4], rv[5]));
    o0.w = h2_to_u(__floats2half2_rn(rv[6], rv[7]));
    o1.x = h2_to_u(__floats2half2_rn(rv[8], rv[9]));
    o1.y = h2_to_u(__floats2half2_rn(rv[10], rv[11]));
    o1.z = h2_to_u(__floats2half2_rn(rv[12], rv[13]));
    o1.w = h2_to_u(__floats2half2_rn(rv[14], rv[15]));
    uint4* op = (uint4*)(g_acc + d * 128 + gl * 16);
    op[0] = o0; op[1] = o1;
    // BN: reduce across the 4 node groups, stage in smem
#pragma unroll
    for (int j = 0; j < 16; j++) {
        float v = rv[j];
        float q = v * v;
        v += __shfl_xor_sync(0xffffffffu, v, 8);
        v += __shfl_xor_sync(0xffffffffu, v, 16);
        q += __shfl_xor_sync(0xffffffffu, q, 8);
        q += __shfl_xor_sync(0xffffffffu, q, 16);
        if (l < 8) {
            atomicAdd(&bns[gl * 16 + j], v);
            atomicAdd(&bnq[gl * 16 + j], q);
        }
    }
    __syncthreads();
    if (t < 128) {
        atomicAdd(&g_bnsum[t], bns[t]);
        atomicAdd(&g_bnsq[t], bnq[t]);
    }
}

// ============ 128x128 GEMM: 256 threads, 128-node tile, 8x8 register blocking (R12) ============
__global__ void __launch_bounds__(256) k_gemm128(const float* __restrict__ W,
                                                 const float* __restrict__ att,
                                                 const float* __restrict__ gam,
                                                 const float* __restrict__ bet) {
    __shared__ float Xs[128][33];    // [node][kk] — staging writes conflict-free
    __shared__ float Ws[32][136];    // [kk][orow] — float4 reads
    __shared__ float A[256];
    __shared__ float Ss[128], Hs[128];
    int t = threadIdx.x;
    int lane = t & 31;
    int row8 = t >> 5;      // 0..7
    int og = t & 15;        // outputs og*8..+8
    int ng = t >> 4;        // 0..15 -> nodes ng*8..+8
    int o0 = og * 8;
    int n0 = blockIdx.x * 128;

    A[t] = att[t];
    if (t < 128) {
        float m = g_bnsum[t] * (1.f / (float)N_NODES);
        float var = g_bnsq[t] * (1.f / (float)N_NODES) - m * m;
        float sc = gam[t] * rsqrtf(var + 1e-5f);
        Ss[t] = sc;
        Hs[t] = bet[t] - m * sc;
    }
    __syncthreads();

    float acc[8][8];
#pragma unroll
    for (int i = 0; i < 8; i++)
#pragma unroll
        for (int q = 0; q < 8; q++) acc[i][q] = 0.f;

    for (int kt = 0; kt < 128; kt += 32) {
        float sc = Ss[kt + lane], sh = Hs[kt + lane];
        // stage X: Xs[r][lane] (conflict-free: stride 33)
#pragma unroll
        for (int p = 0; p < 16; p++) {
            int r = row8 + p * 8;   // 0..127
            float v = __half2float(g_acc[(n0 + r) * 128 + kt + lane]);
            float y = v * sc + sh;
            Xs[r][lane] = (y >= 0.f) ? y : 0.2f * y;
        }
        // stage W transposed: Ws[kk][orow]
#pragma unroll
        for (int p = 0; p < 16; p++) {
            int orow = row8 + p * 8;   // 0..127
            Ws[lane][orow] = W[orow * 128 + kt + lane];
        }
        __syncthreads();
#pragma unroll 4
        for (int kk = 0; kk < 32; kk++) {
            float4 wa = *(const float4*)&Ws[kk][o0];
            float4 wb = *(const float4*)&Ws[kk][o0 + 4];
            float xv[8];
#pragma unroll
            for (int i = 0; i < 8; i++) xv[i] = Xs[ng * 8 + i][kk];
#pragma unroll
            for (int i = 0; i < 8; i++) {
                acc[i][0] += xv[i] * wa.x; acc[i][1] += xv[i] * wa.y;
                acc[i][2] += xv[i] * wa.z; acc[i][3] += xv[i] * wa.w;
                acc[i][4] += xv[i] * wb.x; acc[i][5] += xv[i] * wb.y;
                acc[i][6] += xv[i] * wb.z; acc[i][7] += xv[i] * wb.w;
            }
        }
        __syncthreads();
    }
    int head = og >> 1;
    int c0 = (og & 1) * 8;
#pragma unroll
    for (int i = 0; i < 8; i++) {
        int n = n0 + ng * 8 + i;
        uint4 pack;
        pack.x = h2_to_u(__floats2half2_rn(acc[i][0], acc[i][1]));
        pack.y = h2_to_u(__floats2half2_rn(acc[i][2], acc[i][3]));
        pack.z = h2_to_u(__floats2half2_rn(acc[i][4], acc[i][5]));
        pack.w = h2_to_u(__floats2half2_rn(acc[i][6], acc[i][7]));
        *(uint4*)(g_h + n * 128 + o0) = pack;
        float pd = 0.f, ps = 0.f;
#pragma unroll
        for (int q = 0; q < 8; q++) {
            pd += acc[i][q] * A[head * 32 + c0 + q];
            ps += acc[i][q] * A[head * 32 + 16 + c0 + q];
        }
        pd += __shfl_xor_sync(0xffffffffu, pd, 1);
        ps += __shfl_xor_sync(0xffffffffu, ps, 1);
        if (!(og & 1)) { g_adst[n * 8 + head] = pd; g_srw[n * 8 + head].x = ps; }
    }
}

// ============ power-mean pooling (BN affine inline) + head + CSR counter re-zero ============
__global__ void k_poolsum(const float* __restrict__ pp, const float* __restrict__ gam,
                          const float* __restrict__ bet) {
    float p = pp[0];
    int b = blockIdx.y, chunk = blockIdx.x, c = threadIdx.x;  // 128 threads
    float m = g_bnsum[c] * (1.f / (float)N_NODES);
    float var = g_bnsq[c] * (1.f / (float)N_NODES) - m * m;
    float sc = gam[c] * rsqrtf(var + 1e-5f);
    float sh = bet[c] - m * sc;
    float s = 0.f;
    int i0 = chunk * 313;
    int iend = min(i0 + 313, NODE_PER_G);
    for (int i = i0; i < iend; i++) {
        float v = __half2float(g_acc[(b * NODE_PER_G + i) * 128 + c]);
        float y = v * sc + sh;
        y = (y >= 0.f) ? y : 0.2f * y;
        y = fminf(fmaxf(y, 0.f), 100.f);
        if (p != 1.f) y = (y > 0.f) ? __powf(y, p) : 0.f;
        s += y;
    }
    atomicAdd(&g_pool[b * 128 + c], s);
    // re-zero bump-CSR counters for the next graph replay
    int tid = (b * 32 + chunk) * 128 + c;
    for (int idx = tid; idx < N_NODES; idx += 32 * BATCH * 128) {
        g_cntS[idx] = 0;
        g_cntD[idx] = 0;
    }
}
__global__ void k_final(float* out, int out_size, const float* __restrict__ pp,
                        const float* __restrict__ Wg, const float* __restrict__ bg) {
    __shared__ float xg[1024];
    __shared__ float lg[16];
    int t = threadIdx.x;   // 1024
    float p = pp[0];
    {
        float m = g_pool[t] * (1.f / (float)NODE_PER_G);
        g_pool[t] = 0.f;
        if (t < 128) { g_bnsum[t] = 0.f; g_bnsq[t] = 0.f; }
        m = fminf(fmaxf(m, 0.f), 100.f);
        if (p != 1.f) m = (m > 0.f) ? __powf(m, 1.f / p) : 0.f;
        xg[t] = m;
    }
    __syncthreads();
    if (t < 16) {
        int b = t >> 1, cls = t & 1;
        float a = bg[cls];
        const float* w = Wg + cls * 128;
        const float* xr = xg + b * 128;
        for (int c2 = 0; c2 < 128; c2++) a += xr[c2] * w[c2];
        lg[t] = a;
        if (t < out_size) out[t] = a;
    }
    __syncthreads();
    if (t < 8 && (16 + t) < out_size) {
        out[16 + t] = (lg[2 * t + 1] > lg[2 * t]) ? 1.f : 0.f;
    }
}

// ============================ host driver (11 launches) ============================
extern "C" void kernel_launch(void* const* d_in, const int* in_sizes, int n_in,
                              void* d_out, int out_size) {
    const float* x    = (const float*)d_in[0];
    const int*   ei   = (const int*)d_in[1];
    const float* W1   = (const float*)d_in[2];
    const float* att1 = (const float*)d_in[3];
    const float* b1   = (const float*)d_in[4];
    const float* g1   = (const float*)d_in[5];
    const float* be1  = (const float*)d_in[6];
    const float* W2   = (const float*)d_in[7];
    const float* att2 = (const float*)d_in[8];
    const float* b2   = (const float*)d_in[9];
    const float* g2   = (const float*)d_in[10];
    const float* be2  = (const float*)d_in[11];
    const float* W3   = (const float*)d_in[12];
    const float* att3 = (const float*)d_in[13];
    const float* b3   = (const float*)d_in[14];
    const float* g3   = (const float*)d_in[15];
    const float* be3  = (const float*)d_in[16];
    const float* p    = (const float*)d_in[17];
    const float* Wg   = (const float*)d_in[18];
    const float* bg   = (const float*)d_in[19];
    float* out = (float*)d_out;

    // 1: bump-bucket CSR (both dirs) + layer-1 GEMM (node,head threads) + fused att dots
    k_build_gemm<<<EB + GB1, 256>>>(ei, x, W1, att1);
    // layer 1
    k_srcsoft<<<2500, 256>>>();
    k_gather<<<2500, 256>>>(b1);
    // layer 2
    k_gemm128<<<N_NODES / 128, 256>>>(W2, att2, g1, be1);   // <- profiled slot
    k_srcsoft<<<2500, 256>>>();
    k_gather<<<2500, 256>>>(b2);
    // layer 3
    k_gemm128<<<N_NODES / 128, 256>>>(W3, att3, g2, be2);
    k_srcsoft<<<2500, 256>>>();
    k_gather<<<2500, 256>>>(b3);
    // pooling + head (+ CSR counter re-zero)
    k_poolsum<<<dim3(32, BATCH), 128>>>(p, g3, be3);
    k_final<<<1, 1024>>>(out, out_size, p, Wg, bg);
}

// round 15
// speedup vs baseline: 1.1358x; 1.0335x over previous
#include <cuda_runtime.h>
#include <cuda_fp16.h>
#include <mma.h>
#include <math.h>

using namespace nvcuda;

#define N_NODES 80000
#define E_EDGES 1280000
#define EP_EDGES (E_EDGES + N_NODES)   /* 1,360,000 with self-loops */
#define C 128
#define NHEAD 8
#define NODE_PER_G 10000
#define BATCH 8
#define EB ((EP_EDGES + 255) / 256)    /* 5313 */
#define GB1 2500                        /* N*8/256 layer-1 blocks (thread = node,head) */
#define WSB 64                          /* W2/W3 fp16-split blocks (16384/256) */
#define SLOT 64                         /* max degree bucket (P(deg>63)~1e-17) */
#define GEMM_SMEM 73728                 /* 4 x 128x72 halves; aliased as 128x136 float C */

// ---------------- device scratch ----------------
__device__ __half g_h[N_NODES * C];
__device__ __half g_acc[N_NODES * C];
__device__ float g_adst[N_NODES * NHEAD];
__device__ float2 g_srw[N_NODES * NHEAD];   // .x = asrc dot, .y = 1/(sum exp + 1e-16)
__device__ __half g_Wh[2 * 16384];          // fp16 hi part of W2, W3
__device__ __half g_Wl[2 * 16384];          // fp16 residual part
__device__ int g_cntS[N_NODES];
__device__ int g_cntD[N_NODES];
__device__ int g_slotS[N_NODES * SLOT];  // dst ids grouped by src
__device__ int g_slotD[N_NODES * SLOT];  // src ids grouped by dst
__device__ float g_bnsum[C], g_bnsq[C];
__device__ float g_pool[BATCH * C];

__device__ __forceinline__ float lrelu(float a) { return a >= 0.f ? a : 0.2f * a; }
__device__ __forceinline__ unsigned h2_to_u(__half2 h) {
    union { __half2 h; unsigned u; } cv; cv.h = h; return cv.u;
}
// ---- packed f32x2 helpers (sm_103a FFMA2 path) ----
__device__ __forceinline__ unsigned long long pack2(float lo, float hi) {
    unsigned long long r;
    asm("mov.b64 %0, {%1, %2};" : "=l"(r) : "r"(__float_as_uint(lo)), "r"(__float_as_uint(hi)));
    return r;
}
__device__ __forceinline__ void unpack2(unsigned long long v, float& lo, float& hi) {
    unsigned a, b;
    asm("mov.b64 {%0, %1}, %2;" : "=r"(a), "=r"(b) : "l"(v));
    lo = __uint_as_float(a); hi = __uint_as_float(b);
}
__device__ __forceinline__ void ffma2(unsigned long long& acc, unsigned long long v, unsigned long long w) {
    asm("fma.rn.f32x2 %0, %1, %2, %0;" : "+l"(acc) : "l"(v), "l"(w));
}
__device__ __forceinline__ void acc8(unsigned long long* a, uint4 p, unsigned long long w2) {
    union { unsigned u; __half2 h; } c0, c1, c2, c3;
    c0.u = p.x; c1.u = p.y; c2.u = p.z; c3.u = p.w;
    float2 f0 = __half22float2(c0.h), f1 = __half22float2(c1.h);
    float2 f2 = __half22float2(c2.h), f3 = __half22float2(c3.h);
    ffma2(a[0], pack2(f0.x, f0.y), w2);
    ffma2(a[1], pack2(f1.x, f1.y), w2);
    ffma2(a[2], pack2(f2.x, f2.y), w2);
    ffma2(a[3], pack2(f3.x, f3.y), w2);
}

// ============ kernel 1: CSR build + layer-1 GEMM (node,head) + att dots + W2/W3 fp16 split ============
__global__ void k_build_gemm(const int* __restrict__ ei, const float* __restrict__ xin,
                             const float* __restrict__ W1, const float* __restrict__ att,
                             const float* __restrict__ W2, const float* __restrict__ W3) {
    int b = blockIdx.x, t = threadIdx.x;
    if (b < EB) {
        int e = b * 256 + t;
        if (e < EP_EDGES) {
            int s, d;
            if (e < E_EDGES) { s = ei[e]; d = ei[E_EDGES + e]; } else { s = d = e - E_EDGES; }
            int ps = atomicAdd(&g_cntS[s], 1);
            g_slotS[s * SLOT + ps] = d;
            int pd = atomicAdd(&g_cntD[d], 1);
            g_slotD[d * SLOT + pd] = s;
        }
    } else if (b < EB + GB1) {
        // layer-1 GEMM: one thread per (node, head). W1 in smem, head-stride 132 (conflict-free).
        __shared__ float W1p[8 * 132];   // W1p[h*132 + k*16 + c] = W1[(h*16+c)*8 + k]
        __shared__ float As[256];
        As[t] = att[t];
        for (int idx = t; idx < 1024; idx += 256) {
            int o = idx >> 3, k = idx & 7;
            int h = o >> 4, c = o & 15;
            W1p[h * 132 + k * 16 + c] = W1[idx];
        }
        __syncthreads();
        int id = (b - EB) * 256 + t;   // GB1 blocks -> N*8 threads
        int n = id >> 3, h = id & 7;
        float4 x0 = *(const float4*)(xin + n * 8);
        float4 x1 = *(const float4*)(xin + n * 8 + 4);
        float xk[8] = {x0.x, x0.y, x0.z, x0.w, x1.x, x1.y, x1.z, x1.w};
        float v[16];
#pragma unroll
        for (int c = 0; c < 16; c++) v[c] = 0.f;
        const float* wp = W1p + h * 132;
#pragma unroll
        for (int k = 0; k < 8; k++) {
            float xv = xk[k];
            float4 wa = *(const float4*)(wp + k * 16);
            float4 wb = *(const float4*)(wp + k * 16 + 4);
            float4 wc = *(const float4*)(wp + k * 16 + 8);
            float4 wd = *(const float4*)(wp + k * 16 + 12);
            v[0] += xv * wa.x; v[1] += xv * wa.y; v[2] += xv * wa.z; v[3] += xv * wa.w;
            v[4] += xv * wb.x; v[5] += xv * wb.y; v[6] += xv * wb.z; v[7] += xv * wb.w;
            v[8] += xv * wc.x; v[9] += xv * wc.y; v[10] += xv * wc.z; v[11] += xv * wc.w;
            v[12] += xv * wd.x; v[13] += xv * wd.y; v[14] += xv * wd.z; v[15] += xv * wd.w;
        }
        uint4 p0, p1;
        p0.x = h2_to_u(__floats2half2_rn(v[0], v[1]));
        p0.y = h2_to_u(__floats2half2_rn(v[2], v[3]));
        p0.z = h2_to_u(__floats2half2_rn(v[4], v[5]));
        p0.w = h2_to_u(__floats2half2_rn(v[6], v[7]));
        p1.x = h2_to_u(__floats2half2_rn(v[8], v[9]));
        p1.y = h2_to_u(__floats2half2_rn(v[10], v[11]));
        p1.z = h2_to_u(__floats2half2_rn(v[12], v[13]));
        p1.w = h2_to_u(__floats2half2_rn(v[14], v[15]));
        uint4* hp = (uint4*)(g_h + n * 128 + h * 16);
        hp[0] = p0; hp[1] = p1;
        float pd = 0.f, ps = 0.f;
        const float* a1 = As + h * 32;
#pragma unroll
        for (int c = 0; c < 16; c++) {
            pd += v[c] * a1[c];
            ps += v[c] * a1[16 + c];
        }
        g_adst[id] = pd;
        g_srw[id].x = ps;
    } else {
        // W2/W3 fp16 residual split (64 blocks x 256 = 16384 elems each)
        int e = (b - EB - GB1) * 256 + t;
        float w2 = W2[e];
        __half h2 = __float2half_rn(w2);
        g_Wh[e] = h2;
        g_Wl[e] = __float2half_rn(w2 - __half2float(h2));
        float w3 = W3[e];
        __half h3 = __float2half_rn(w3);
        g_Wh[16384 + e] = h3;
        g_Wl[16384 + e] = __float2half_rn(w3 - __half2float(h3));
    }
}

// ============ src-grouped softmax denominators + BN-stat zeroing ============
__global__ void k_srcsoft() {
    if (blockIdx.x == 0 && threadIdx.x < 128) {   // zero BN stats for the gather that follows
        g_bnsum[threadIdx.x] = 0.f;
        g_bnsq[threadIdx.x] = 0.f;
    }
    int id = blockIdx.x * 256 + threadIdx.x;   // 2500 blocks, thread = (src, head)
    int s = id >> 3, h = id & 7;
    float as = g_srw[id].x;
    int i = s * SLOT;
    int end = i + g_cntS[s];
    float den = 0.f;
    for (; i + 2 <= end; i += 2) {
        int d0 = g_slotS[i], d1 = g_slotS[i + 1];
        den += __expf(lrelu(g_adst[d0 * 8 + h] + as)) + __expf(lrelu(g_adst[d1 * 8 + h] + as));
    }
    if (i < end) {
        int d = g_slotS[i];
        den += __expf(lrelu(g_adst[d * 8 + h] + as));
    }
    g_srw[id].y = 1.f / (den + 1e-16f);
}

// ============ gather: 8 lanes per dst (lane == head), FFMA2, fused BN stats, unroll 4 ============
__global__ void __launch_bounds__(256) k_gather(const float* __restrict__ bias) {
    __shared__ float bns[128], bnq[128];
    int t = threadIdx.x;
    if (t < 128) { bns[t] = 0.f; bnq[t] = 0.f; }
    __syncthreads();
    int warp = t >> 5, l = t & 31;
    int g = l >> 3;          // node group within warp (0..3)
    int gl = l & 7;          // lane within group == head index
    int d = blockIdx.x * 32 + warp * 4 + g;   // grid 2500 -> 32 nodes/block
    float adh = g_adst[d * 8 + gl];
    int i = d * SLOT;
    int end = i + g_cntD[d];
    unsigned long long acc[8];
#pragma unroll
    for (int j = 0; j < 8; j++) acc[j] = 0ULL;
    const __half* hrow = g_h;
    for (; i + 4 <= end; i += 4) {
        int s0 = g_slotD[i], s1 = g_slotD[i + 1];
        int s2 = g_slotD[i + 2], s3 = g_slotD[i + 3];
        float2 sw0 = g_srw[s0 * 8 + gl];
        float2 sw1 = g_srw[s1 * 8 + gl];
        float2 sw2 = g_srw[s2 * 8 + gl];
        float2 sw3 = g_srw[s3 * 8 + gl];
        const uint4* r0 = (const uint4*)(hrow + s0 * 128 + gl * 16);
        const uint4* r1 = (const uint4*)(hrow + s1 * 128 + gl * 16);
        const uint4* r2 = (const uint4*)(hrow + s2 * 128 + gl * 16);
        const uint4* r3 = (const uint4*)(hrow + s3 * 128 + gl * 16);
        uint4 p0 = r0[0], q0 = r0[1];
        uint4 p1 = r1[0], q1 = r1[1];
        uint4 p2 = r2[0], q2 = r2[1];
        uint4 p3 = r3[0], q3 = r3[1];
        float w0 = __expf(lrelu(adh + sw0.x)) * sw0.y;
        float w1 = __expf(lrelu(adh + sw1.x)) * sw1.y;
        float w2 = __expf(lrelu(adh + sw2.x)) * sw2.y;
        float w3 = __expf(lrelu(adh + sw3.x)) * sw3.y;
        unsigned long long w20 = pack2(w0, w0), w21 = pack2(w1, w1);
        unsigned long long w22 = pack2(w2, w2), w23 = pack2(w3, w3);
        acc8(acc, p0, w20); acc8(acc + 4, q0, w20);
        acc8(acc, p1, w21); acc8(acc + 4, q1, w21);
        acc8(acc, p2, w22); acc8(acc + 4, q2, w22);
        acc8(acc, p3, w23); acc8(acc + 4, q3, w23);
    }
    for (; i < end; i++) {
        int s = g_slotD[i];
        float2 sw = g_srw[s * 8 + gl];
        float w = __expf(lrelu(adh + sw.x)) * sw.y;
        const uint4* r = (const uint4*)(hrow + s * 128 + gl * 16);
        uint4 p = r[0], q = r[1];
        unsigned long long w2 = pack2(w, w);
        acc8(acc, p, w2); acc8(acc + 4, q, w2);
    }
    // epilogue: bias + relu, fp16 store, BN partial sums
    float rv[16];
#pragma unroll
    for (int j = 0; j < 8; j++) unpack2(acc[j], rv[2 * j], rv[2 * j + 1]);
    const float4* bp = (const float4*)(bias + gl * 16);
#pragma unroll
    for (int j = 0; j < 4; j++) {
        float4 b4 = bp[j];
        rv[4 * j + 0] = fmaxf(rv[4 * j + 0] + b4.x, 0.f);
        rv[4 * j + 1] = fmaxf(rv[4 * j + 1] + b4.y, 0.f);
        rv[4 * j + 2] = fmaxf(rv[4 * j + 2] + b4.z, 0.f);
        rv[4 * j + 3] = fmaxf(rv[4 * j + 3] + b4.w, 0.f);
    }
    uint4 o0, o1;
    o0.x = h2_to_u(__floats2half2_rn(rv[0], rv[1]));
    o0.y = h2_to_u(__floats2half2_rn(rv[2], rv[3]));
    o0.z = h2_to_u(__floats2half2_rn(rv[4], rv[5]));
    o0.w = h2_to_u(__floats2half2_rn(rv[6], rv[7]));
    o1.x = h2_to_u(__floats2half2_rn(rv[8], rv[9]));
    o1.y = h2_to_u(__floats2half2_rn(rv[10], rv[11]));
    o1.z = h2_to_u(__floats2half2_rn(rv[12], rv[13]));
    o1.w = h2_to_u(__floats2half2_rn(rv[14], rv[15]));
    uint4* op = (uint4*)(g_acc + d * 128 + gl * 16);
    op[0] = o0; op[1] = o1;
    // BN: reduce across the 4 node groups, stage in smem
#pragma unroll
    for (int j = 0; j < 16; j++) {
        float v = rv[j];
        float q = v * v;
        v += __shfl_xor_sync(0xffffffffu, v, 8);
        v += __shfl_xor_sync(0xffffffffu, v, 16);
        q += __shfl_xor_sync(0xffffffffu, q, 8);
        q += __shfl_xor_sync(0xffffffffu, q, 16);
        if (l < 8) {
            atomicAdd(&bns[gl * 16 + j], v);
            atomicAdd(&bnq[gl * 16 + j], q);
        }
    }
    __syncthreads();
    if (t < 128) {
        atomicAdd(&g_bnsum[t], bns[t]);
        atomicAdd(&g_bnsq[t], bnq[t]);
    }
}

// ============ 128x128 GEMM via HMMA (wmma), residual split, smem-staged W ============
// smem layout (dynamic, GEMM_SMEM bytes):
//   Xh[128][72], Xl[128][72], Wh[128][72], Wl[128][72] halves (K staged in 2 halves of 64)
//   after MMA: aliased as Cs float[128][136]
__global__ void __launch_bounds__(256) k_gemm128(int wsel,
                                                 const float* __restrict__ att,
                                                 const float* __restrict__ gam,
                                                 const float* __restrict__ bet) {
    extern __shared__ char sm[];
    __half* Xh = (__half*)sm;                       // 128*72
    __half* Xl = Xh + 128 * 72;
    __half* Wsh = Xl + 128 * 72;                    // [out][k] 128*72
    __half* Wsl = Wsh + 128 * 72;
    float* Cs = (float*)sm;                         // 128*136 floats (after MMA)
    __shared__ float A[256];
    __shared__ float Ss[128], Hs[128];
    int t = threadIdx.x;
    int n0 = blockIdx.x * 128;
    const __half* Wh = g_Wh + wsel * 16384;
    const __half* Wl = g_Wl + wsel * 16384;

    A[t] = att[t];
    if (t < 128) {
        float m = g_bnsum[t] * (1.f / (float)N_NODES);
        float var = g_bnsq[t] * (1.f / (float)N_NODES) - m * m;
        float sc = gam[t] * rsqrtf(var + 1e-5f);
        Ss[t] = sc;
        Hs[t] = bet[t] - m * sc;
    }
    __syncthreads();

    int wid = t >> 5;   // 8 warps, warp owns rows wid*16..+16, all 128 cols
    wmma::fragment<wmma::accumulator, 16, 16, 16, float> acc[8];
#pragma unroll
    for (int cg = 0; cg < 8; cg++) wmma::fill_fragment(acc[cg], 0.f);
    wmma::fragment<wmma::matrix_a, 16, 16, 16, __half, wmma::row_major> ah, al;
    wmma::fragment<wmma::matrix_b, 16, 16, 16, __half, wmma::col_major> bh, bl;

#pragma unroll
    for (int kh = 0; kh < 2; kh++) {
        // stage X half: lrelu(affine(g_acc)) -> fp16 + residual
        for (int idx = t; idx < 128 * 64; idx += 256) {
            int n = idx >> 6, k = idx & 63;
            int kg = kh * 64 + k;
            float v = __half2float(g_acc[(n0 + n) * 128 + kg]);
            float y = v * Ss[kg] + Hs[kg];
            y = (y >= 0.f) ? y : 0.2f * y;
            __half xh = __float2half_rn(y);
            Xh[n * 72 + k] = xh;
            Xl[n * 72 + k] = __float2half_rn(y - __half2float(xh));
        }
        // stage W half (fp16 split, precomputed)
        for (int idx = t; idx < 128 * 64; idx += 256) {
            int o = idx >> 6, k = idx & 63;
            Wsh[o * 72 + k] = Wh[o * 128 + kh * 64 + k];
            Wsl[o * 72 + k] = Wl[o * 128 + kh * 64 + k];
        }
        __syncthreads();
#pragma unroll
        for (int k0 = 0; k0 < 4; k0++) {
            wmma::load_matrix_sync(ah, Xh + wid * 16 * 72 + k0 * 16, 72);
            wmma::load_matrix_sync(al, Xl + wid * 16 * 72 + k0 * 16, 72);
#pragma unroll
            for (int cg = 0; cg < 8; cg++) {
                wmma::load_matrix_sync(bh, Wsh + (cg * 16) * 72 + k0 * 16, 72);
                wmma::load_matrix_sync(bl, Wsl + (cg * 16) * 72 + k0 * 16, 72);
                wmma::mma_sync(acc[cg], ah, bh, acc[cg]);
                wmma::mma_sync(acc[cg], ah, bl, acc[cg]);
                wmma::mma_sync(acc[cg], al, bh, acc[cg]);
            }
        }
        __syncthreads();   // mma reads done before restaging / C store
    }
#pragma unroll
    for (int cg = 0; cg < 8; cg++)
        wmma::store_matrix_sync(Cs + wid * 16 * 136 + cg * 16, acc[cg], 136, wmma::mem_row_major);
    __syncthreads();

    // epilogue: fp16 h store + attention dots (identical mapping to SIMT version)
    int og = t & 15, ng = t >> 4;
    int o0 = og * 8;
    int head = og >> 1;
    int c0 = (og & 1) * 8;
#pragma unroll
    for (int i = 0; i < 8; i++) {
        int nl = ng * 8 + i;
        int n = n0 + nl;
        float v[8];
#pragma unroll
        for (int q = 0; q < 8; q++) v[q] = Cs[nl * 136 + o0 + q];
        uint4 pack;
        pack.x = h2_to_u(__floats2half2_rn(v[0], v[1]));
        pack.y = h2_to_u(__floats2half2_rn(v[2], v[3]));
        pack.z = h2_to_u(__floats2half2_rn(v[4], v[5]));
        pack.w = h2_to_u(__floats2half2_rn(v[6], v[7]));
        *(uint4*)(g_h + n * 128 + o0) = pack;
        float pd = 0.f, ps = 0.f;
#pragma unroll
        for (int q = 0; q < 8; q++) {
            pd += v[q] * A[head * 32 + c0 + q];
            ps += v[q] * A[head * 32 + 16 + c0 + q];
        }
        pd += __shfl_xor_sync(0xffffffffu, pd, 1);
        ps += __shfl_xor_sync(0xffffffffu, ps, 1);
        if (!(og & 1)) { g_adst[n * 8 + head] = pd; g_srw[n * 8 + head].x = ps; }
    }
}

// ============ power-mean pooling (BN affine inline) + head + CSR counter re-zero ============
__global__ void k_poolsum(const float* __restrict__ pp, const float* __restrict__ gam,
                          const float* __restrict__ bet) {
    float p = pp[0];
    int b = blockIdx.y, chunk = blockIdx.x, c = threadIdx.x;  // 128 threads
    float m = g_bnsum[c] * (1.f / (float)N_NODES);
    float var = g_bnsq[c] * (1.f / (float)N_NODES) - m * m;
    float sc = gam[c] * rsqrtf(var + 1e-5f);
    float sh = bet[c] - m * sc;
    float s = 0.f;
    int i0 = chunk * 313;
    int iend = min(i0 + 313, NODE_PER_G);
    for (int i = i0; i < iend; i++) {
        float v = __half2float(g_acc[(b * NODE_PER_G + i) * 128 + c]);
        float y = v * sc + sh;
        y = (y >= 0.f) ? y : 0.2f * y;
        y = fminf(fmaxf(y, 0.f), 100.f);
        if (p != 1.f) y = (y > 0.f) ? __powf(y, p) : 0.f;
        s += y;
    }
    atomicAdd(&g_pool[b * 128 + c], s);
    // re-zero bump-CSR counters for the next graph replay
    int tid = (b * 32 + chunk) * 128 + c;
    for (int idx = tid; idx < N_NODES; idx += 32 * BATCH * 128) {
        g_cntS[idx] = 0;
        g_cntD[idx] = 0;
    }
}
__global__ void k_final(float* out, int out_size, const float* __restrict__ pp,
                        const float* __restrict__ Wg, const float* __restrict__ bg) {
    __shared__ float xg[1024];
    __shared__ float lg[16];
    int t = threadIdx.x;   // 1024
    float p = pp[0];
    {
        float m = g_pool[t] * (1.f / (float)NODE_PER_G);
        g_pool[t] = 0.f;
        if (t < 128) { g_bnsum[t] = 0.f; g_bnsq[t] = 0.f; }
        m = fminf(fmaxf(m, 0.f), 100.f);
        if (p != 1.f) m = (m > 0.f) ? __powf(m, 1.f / p) : 0.f;
        xg[t] = m;
    }
    __syncthreads();
    if (t < 16) {
        int b = t >> 1, cls = t & 1;
        float a = bg[cls];
        const float* w = Wg + cls * 128;
        const float* xr = xg + b * 128;
        for (int c2 = 0; c2 < 128; c2++) a += xr[c2] * w[c2];
        lg[t] = a;
        if (t < out_size) out[t] = a;
    }
    __syncthreads();
    if (t < 8 && (16 + t) < out_size) {
        out[16 + t] = (lg[2 * t + 1] > lg[2 * t]) ? 1.f : 0.f;
    }
}

// ============================ host driver (11 launches) ============================
extern "C" void kernel_launch(void* const* d_in, const int* in_sizes, int n_in,
                              void* d_out, int out_size) {
    const float* x    = (const float*)d_in[0];
    const int*   ei   = (const int*)d_in[1];
    const float* W1   = (const float*)d_in[2];
    const float* att1 = (const float*)d_in[3];
    const float* b1   = (const float*)d_in[4];
    const float* g1   = (const float*)d_in[5];
    const float* be1  = (const float*)d_in[6];
    const float* W2   = (const float*)d_in[7];
    const float* att2 = (const float*)d_in[8];
    const float* b2   = (const float*)d_in[9];
    const float* g2   = (const float*)d_in[10];
    const float* be2  = (const float*)d_in[11];
    const float* W3   = (const float*)d_in[12];
    const float* att3 = (const float*)d_in[13];
    const float* b3   = (const float*)d_in[14];
    const float* g3   = (const float*)d_in[15];
    const float* be3  = (const float*)d_in[16];
    const float* p    = (const float*)d_in[17];
    const float* Wg   = (const float*)d_in[18];
    const float* bg   = (const float*)d_in[19];
    float* out = (float*)d_out;

    static bool attr_set = false;
    if (!attr_set) {
        cudaFuncSetAttribute(k_gemm128, cudaFuncAttributeMaxDynamicSharedMemorySize, GEMM_SMEM);
        attr_set = true;
    }

    // 1: bump-bucket CSR + layer-1 GEMM + att dots + W2/W3 fp16 split
    k_build_gemm<<<EB + GB1 + WSB, 256>>>(ei, x, W1, att1, W2, W3);
    // layer 1
    k_srcsoft<<<2500, 256>>>();
    k_gather<<<2500, 256>>>(b1);
    // layer 2
    k_gemm128<<<N_NODES / 128, 256, GEMM_SMEM>>>(0, att2, g1, be1);   // <- profiled slot
    k_srcsoft<<<2500, 256>>>();
    k_gather<<<2500, 256>>>(b2);
    // layer 3
    k_gemm128<<<N_NODES / 128, 256, GEMM_SMEM>>>(1, att3, g2, be2);
    k_srcsoft<<<2500, 256>>>();
    k_gather<<<2500, 256>>>(b3);
    // pooling + head (+ CSR counter re-zero)
    k_poolsum<<<dim3(32, BATCH), 128>>>(p, g3, be3);
    k_final<<<1, 1024>>>(out, out_size, p, Wg, bg);
}

// round 16
// speedup vs baseline: 1.2066x; 1.0624x over previous
#include <cuda_runtime.h>
#include <cuda_fp16.h>
#include <mma.h>
#include <math.h>

using namespace nvcuda;

#define N_NODES 80000
#define E_EDGES 1280000
#define EP_EDGES (E_EDGES + N_NODES)   /* 1,360,000 with self-loops */
#define C 128
#define NHEAD 8
#define NODE_PER_G 10000
#define BATCH 8
#define EB ((EP_EDGES + 255) / 256)    /* 5313 */
#define GB1 2500                        /* N*8/256 layer-1 blocks (thread = node,head) */
#define WSB 64                          /* W2/W3 fp16-split blocks (16384/256) */
#define SLOT 64                         /* max degree bucket (P(deg>63)~1e-17) */
#define GEMM_SMEM 55296                 /* Xh/Xl 64x72 + Wh/Wl 128x72 halves; aliased C 64x136 f32 */

// ---------------- device scratch ----------------
__device__ __half g_h[N_NODES * C];
__device__ __half g_acc[N_NODES * C];
__device__ float g_adst[N_NODES * NHEAD];
__device__ float2 g_srw[N_NODES * NHEAD];   // .x = asrc dot, .y = 1/(sum exp + 1e-16)
__device__ __half g_Wh[2 * 16384];          // fp16 hi part of W2, W3
__device__ __half g_Wl[2 * 16384];          // fp16 residual part
__device__ int g_cntS[N_NODES];
__device__ int g_cntD[N_NODES];
__device__ int g_slotS[N_NODES * SLOT];  // dst ids grouped by src
__device__ int g_slotD[N_NODES * SLOT];  // src ids grouped by dst
__device__ float g_bnsum[C], g_bnsq[C];
__device__ float g_pool[BATCH * C];

__device__ __forceinline__ float lrelu(float a) { return a >= 0.f ? a : 0.2f * a; }
__device__ __forceinline__ unsigned h2_to_u(__half2 h) {
    union { __half2 h; unsigned u; } cv; cv.h = h; return cv.u;
}
// ---- packed f32x2 helpers (sm_103a FFMA2 path) ----
__device__ __forceinline__ unsigned long long pack2(float lo, float hi) {
    unsigned long long r;
    asm("mov.b64 %0, {%1, %2};" : "=l"(r) : "r"(__float_as_uint(lo)), "r"(__float_as_uint(hi)));
    return r;
}
__device__ __forceinline__ void unpack2(unsigned long long v, float& lo, float& hi) {
    unsigned a, b;
    asm("mov.b64 {%0, %1}, %2;" : "=r"(a), "=r"(b) : "l"(v));
    lo = __uint_as_float(a); hi = __uint_as_float(b);
}
__device__ __forceinline__ void ffma2(unsigned long long& acc, unsigned long long v, unsigned long long w) {
    asm("fma.rn.f32x2 %0, %1, %2, %0;" : "+l"(acc) : "l"(v), "l"(w));
}
__device__ __forceinline__ void acc8(unsigned long long* a, uint4 p, unsigned long long w2) {
    union { unsigned u; __half2 h; } c0, c1, c2, c3;
    c0.u = p.x; c1.u = p.y; c2.u = p.z; c3.u = p.w;
    float2 f0 = __half22float2(c0.h), f1 = __half22float2(c1.h);
    float2 f2 = __half22float2(c2.h), f3 = __half22float2(c3.h);
    ffma2(a[0], pack2(f0.x, f0.y), w2);
    ffma2(a[1], pack2(f1.x, f1.y), w2);
    ffma2(a[2], pack2(f2.x, f2.y), w2);
    ffma2(a[3], pack2(f3.x, f3.y), w2);
}

// ============ kernel 1: CSR build + layer-1 GEMM (node,head) + att dots + W2/W3 fp16 split ============
__global__ void k_build_gemm(const int* __restrict__ ei, const float* __restrict__ xin,
                             const float* __restrict__ W1, const float* __restrict__ att,
                             const float* __restrict__ W2, const float* __restrict__ W3) {
    int b = blockIdx.x, t = threadIdx.x;
    if (b < EB) {
        int e = b * 256 + t;
        if (e < EP_EDGES) {
            int s, d;
            if (e < E_EDGES) { s = ei[e]; d = ei[E_EDGES + e]; } else { s = d = e - E_EDGES; }
            int ps = atomicAdd(&g_cntS[s], 1);
            g_slotS[s * SLOT + ps] = d;
            int pd = atomicAdd(&g_cntD[d], 1);
            g_slotD[d * SLOT + pd] = s;
        }
    } else if (b < EB + GB1) {
        // layer-1 GEMM: one thread per (node, head). W1 in smem, head-stride 132 (conflict-free).
        __shared__ float W1p[8 * 132];   // W1p[h*132 + k*16 + c] = W1[(h*16+c)*8 + k]
        __shared__ float As[256];
        As[t] = att[t];
        for (int idx = t; idx < 1024; idx += 256) {
            int o = idx >> 3, k = idx & 7;
            int h = o >> 4, c = o & 15;
            W1p[h * 132 + k * 16 + c] = W1[idx];
        }
        __syncthreads();
        int id = (b - EB) * 256 + t;   // GB1 blocks -> N*8 threads
        int n = id >> 3, h = id & 7;
        float4 x0 = *(const float4*)(xin + n * 8);
        float4 x1 = *(const float4*)(xin + n * 8 + 4);
        float xk[8] = {x0.x, x0.y, x0.z, x0.w, x1.x, x1.y, x1.z, x1.w};
        float v[16];
#pragma unroll
        for (int c = 0; c < 16; c++) v[c] = 0.f;
        const float* wp = W1p + h * 132;
#pragma unroll
        for (int k = 0; k < 8; k++) {
            float xv = xk[k];
            float4 wa = *(const float4*)(wp + k * 16);
            float4 wb = *(const float4*)(wp + k * 16 + 4);
            float4 wc = *(const float4*)(wp + k * 16 + 8);
            float4 wd = *(const float4*)(wp + k * 16 + 12);
            v[0] += xv * wa.x; v[1] += xv * wa.y; v[2] += xv * wa.z; v[3] += xv * wa.w;
            v[4] += xv * wb.x; v[5] += xv * wb.y; v[6] += xv * wb.z; v[7] += xv * wb.w;
            v[8] += xv * wc.x; v[9] += xv * wc.y; v[10] += xv * wc.z; v[11] += xv * wc.w;
            v[12] += xv * wd.x; v[13] += xv * wd.y; v[14] += xv * wd.z; v[15] += xv * wd.w;
        }
        uint4 p0, p1;
        p0.x = h2_to_u(__floats2half2_rn(v[0], v[1]));
        p0.y = h2_to_u(__floats2half2_rn(v[2], v[3]));
        p0.z = h2_to_u(__floats2half2_rn(v[4], v[5]));
        p0.w = h2_to_u(__floats2half2_rn(v[6], v[7]));
        p1.x = h2_to_u(__floats2half2_rn(v[8], v[9]));
        p1.y = h2_to_u(__floats2half2_rn(v[10], v[11]));
        p1.z = h2_to_u(__floats2half2_rn(v[12], v[13]));
        p1.w = h2_to_u(__floats2half2_rn(v[14], v[15]));
        uint4* hp = (uint4*)(g_h + n * 128 + h * 16);
        hp[0] = p0; hp[1] = p1;
        float pd = 0.f, ps = 0.f;
        const float* a1 = As + h * 32;
#pragma unroll
        for (int c = 0; c < 16; c++) {
            pd += v[c] * a1[c];
            ps += v[c] * a1[16 + c];
        }
        g_adst[id] = pd;
        g_srw[id].x = ps;
    } else {
        // W2/W3 fp16 residual split (64 blocks x 256 = 16384 elems each)
        int e = (b - EB - GB1) * 256 + t;
        float w2 = W2[e];
        __half h2 = __float2half_rn(w2);
        g_Wh[e] = h2;
        g_Wl[e] = __float2half_rn(w2 - __half2float(h2));
        float w3 = W3[e];
        __half h3 = __float2half_rn(w3);
        g_Wh[16384 + e] = h3;
        g_Wl[16384 + e] = __float2half_rn(w3 - __half2float(h3));
    }
}

// ============ src-grouped softmax denominators + BN-stat zeroing ============
__global__ void k_srcsoft() {
    if (blockIdx.x == 0 && threadIdx.x < 128) {   // zero BN stats for the gather that follows
        g_bnsum[threadIdx.x] = 0.f;
        g_bnsq[threadIdx.x] = 0.f;
    }
    int id = blockIdx.x * 256 + threadIdx.x;   // 2500 blocks, thread = (src, head)
    int s = id >> 3, h = id & 7;
    float as = g_srw[id].x;
    int i = s * SLOT;
    int end = i + g_cntS[s];
    float den = 0.f;
    for (; i + 2 <= end; i += 2) {
        int d0 = g_slotS[i], d1 = g_slotS[i + 1];
        den += __expf(lrelu(g_adst[d0 * 8 + h] + as)) + __expf(lrelu(g_adst[d1 * 8 + h] + as));
    }
    if (i < end) {
        int d = g_slotS[i];
        den += __expf(lrelu(g_adst[d * 8 + h] + as));
    }
    g_srw[id].y = 1.f / (den + 1e-16f);
}

// ============ gather: 8 lanes per dst (lane == head), FFMA2, fused BN stats, unroll 4 ============
__global__ void __launch_bounds__(256) k_gather(const float* __restrict__ bias) {
    __shared__ float bns[128], bnq[128];
    int t = threadIdx.x;
    if (t < 128) { bns[t] = 0.f; bnq[t] = 0.f; }
    __syncthreads();
    int warp = t >> 5, l = t & 31;
    int g = l >> 3;          // node group within warp (0..3)
    int gl = l & 7;          // lane within group == head index
    int d = blockIdx.x * 32 + warp * 4 + g;   // grid 2500 -> 32 nodes/block
    float adh = g_adst[d * 8 + gl];
    int i = d * SLOT;
    int end = i + g_cntD[d];
    unsigned long long acc[8];
#pragma unroll
    for (int j = 0; j < 8; j++) acc[j] = 0ULL;
    const __half* hrow = g_h;
    for (; i + 4 <= end; i += 4) {
        int s0 = g_slotD[i], s1 = g_slotD[i + 1];
        int s2 = g_slotD[i + 2], s3 = g_slotD[i + 3];
        float2 sw0 = g_srw[s0 * 8 + gl];
        float2 sw1 = g_srw[s1 * 8 + gl];
        float2 sw2 = g_srw[s2 * 8 + gl];
        float2 sw3 = g_srw[s3 * 8 + gl];
        const uint4* r0 = (const uint4*)(hrow + s0 * 128 + gl * 16);
        const uint4* r1 = (const uint4*)(hrow + s1 * 128 + gl * 16);
        const uint4* r2 = (const uint4*)(hrow + s2 * 128 + gl * 16);
        const uint4* r3 = (const uint4*)(hrow + s3 * 128 + gl * 16);
        uint4 p0 = r0[0], q0 = r0[1];
        uint4 p1 = r1[0], q1 = r1[1];
        uint4 p2 = r2[0], q2 = r2[1];
        uint4 p3 = r3[0], q3 = r3[1];
        float w0 = __expf(lrelu(adh + sw0.x)) * sw0.y;
        float w1 = __expf(lrelu(adh + sw1.x)) * sw1.y;
        float w2 = __expf(lrelu(adh + sw2.x)) * sw2.y;
        float w3 = __expf(lrelu(adh + sw3.x)) * sw3.y;
        unsigned long long w20 = pack2(w0, w0), w21 = pack2(w1, w1);
        unsigned long long w22 = pack2(w2, w2), w23 = pack2(w3, w3);
        acc8(acc, p0, w20); acc8(acc + 4, q0, w20);
        acc8(acc, p1, w21); acc8(acc + 4, q1, w21);
        acc8(acc, p2, w22); acc8(acc + 4, q2, w22);
        acc8(acc, p3, w23); acc8(acc + 4, q3, w23);
    }
    for (; i < end; i++) {
        int s = g_slotD[i];
        float2 sw = g_srw[s * 8 + gl];
        float w = __expf(lrelu(adh + sw.x)) * sw.y;
        const uint4* r = (const uint4*)(hrow + s * 128 + gl * 16);
        uint4 p = r[0], q = r[1];
        unsigned long long w2 = pack2(w, w);
        acc8(acc, p, w2); acc8(acc + 4, q, w2);
    }
    // epilogue: bias + relu, fp16 store, BN partial sums
    float rv[16];
#pragma unroll
    for (int j = 0; j < 8; j++) unpack2(acc[j], rv[2 * j], rv[2 * j + 1]);
    const float4* bp = (const float4*)(bias + gl * 16);
#pragma unroll
    for (int j = 0; j < 4; j++) {
        float4 b4 = bp[j];
        rv[4 * j + 0] = fmaxf(rv[4 * j + 0] + b4.x, 0.f);
        rv[4 * j + 1] = fmaxf(rv[4 * j + 1] + b4.y, 0.f);
        rv[4 * j + 2] = fmaxf(rv[4 * j + 2] + b4.z, 0.f);
        rv[4 * j + 3] = fmaxf(rv[4 * j + 3] + b4.w, 0.f);
    }
    uint4 o0, o1;
    o0.x = h2_to_u(__floats2half2_rn(rv[0], rv[1]));
    o0.y = h2_to_u(__floats2half2_rn(rv[2], rv[3]));
    o0.z = h2_to_u(__floats2half2_rn(rv[4], rv[5]));
    o0.w = h2_to_u(__floats2half2_rn(rv[6], rv[7]));
    o1.x = h2_to_u(__floats2half2_rn(rv[8], rv[9]));
    o1.y = h2_to_u(__floats2half2_rn(rv[10], rv[11]));
    o1.z = h2_to_u(__floats2half2_rn(rv[12], rv[13]));
    o1.w = h2_to_u(__floats2half2_rn(rv[14], rv[15]));
    uint4* op = (uint4*)(g_acc + d * 128 + gl * 16);
    op[0] = o0; op[1] = o1;
    // BN: reduce across the 4 node groups, stage in smem
#pragma unroll
    for (int j = 0; j < 16; j++) {
        float v = rv[j];
        float q = v * v;
        v += __shfl_xor_sync(0xffffffffu, v, 8);
        v += __shfl_xor_sync(0xffffffffu, v, 16);
        q += __shfl_xor_sync(0xffffffffu, q, 8);
        q += __shfl_xor_sync(0xffffffffu, q, 16);
        if (l < 8) {
            atomicAdd(&bns[gl * 16 + j], v);
            atomicAdd(&bnq[gl * 16 + j], q);
        }
    }
    __syncthreads();
    if (t < 128) {
        atomicAdd(&g_bnsum[t], bns[t]);
        atomicAdd(&g_bnsq[t], bnq[t]);
    }
}

// ============ 128x128 GEMM via HMMA: 64-node tiles, 2 CTAs/SM, residual split ============
// smem: Xh[64][72], Xl[64][72], Wh[128][72], Wl[128][72] (K in 2 halves); aliased Cs float[64][136]
__global__ void __launch_bounds__(256, 2) k_gemm128(int wsel,
                                                    const float* __restrict__ att,
                                                    const float* __restrict__ gam,
                                                    const float* __restrict__ bet) {
    extern __shared__ char sm[];
    __half* Xh = (__half*)sm;                       // 64*72
    __half* Xl = Xh + 64 * 72;
    __half* Wsh = Xl + 64 * 72;                     // [out][k] 128*72
    __half* Wsl = Wsh + 128 * 72;
    float* Cs = (float*)sm;                         // 64*136 floats (after MMA)
    __shared__ float A[256];
    __shared__ float Ss[128], Hs[128];
    int t = threadIdx.x;
    int n0 = blockIdx.x * 64;
    const __half* Wh = g_Wh + wsel * 16384;
    const __half* Wl = g_Wl + wsel * 16384;

    A[t] = att[t];
    if (t < 128) {
        float m = g_bnsum[t] * (1.f / (float)N_NODES);
        float var = g_bnsq[t] * (1.f / (float)N_NODES) - m * m;
        float sc = gam[t] * rsqrtf(var + 1e-5f);
        Ss[t] = sc;
        Hs[t] = bet[t] - m * sc;
    }
    __syncthreads();

    int wid = t >> 5;        // 8 warps
    int wr = wid & 3;        // rows wr*16..+16 (64 rows total)
    int wc = wid >> 2;       // cols wc*64..+64
    wmma::fragment<wmma::accumulator, 16, 16, 16, float> acc[4];
#pragma unroll
    for (int cg = 0; cg < 4; cg++) wmma::fill_fragment(acc[cg], 0.f);
    wmma::fragment<wmma::matrix_a, 16, 16, 16, __half, wmma::row_major> ah, al;
    wmma::fragment<wmma::matrix_b, 16, 16, 16, __half, wmma::col_major> bh, bl;

#pragma unroll
    for (int kh = 0; kh < 2; kh++) {
        // stage X half: lrelu(affine(g_acc)) -> fp16 + residual  (64x64)
        for (int idx = t; idx < 64 * 64; idx += 256) {
            int n = idx >> 6, k = idx & 63;
            int kg = kh * 64 + k;
            float v = __half2float(g_acc[(n0 + n) * 128 + kg]);
            float y = v * Ss[kg] + Hs[kg];
            y = (y >= 0.f) ? y : 0.2f * y;
            __half xh = __float2half_rn(y);
            Xh[n * 72 + k] = xh;
            Xl[n * 72 + k] = __float2half_rn(y - __half2float(xh));
        }
        // stage W half (fp16 split, precomputed)  (128x64)
        for (int idx = t; idx < 128 * 64; idx += 256) {
            int o = idx >> 6, k = idx & 63;
            Wsh[o * 72 + k] = Wh[o * 128 + kh * 64 + k];
            Wsl[o * 72 + k] = Wl[o * 128 + kh * 64 + k];
        }
        __syncthreads();
#pragma unroll
        for (int k0 = 0; k0 < 4; k0++) {
            wmma::load_matrix_sync(ah, Xh + wr * 16 * 72 + k0 * 16, 72);
            wmma::load_matrix_sync(al, Xl + wr * 16 * 72 + k0 * 16, 72);
#pragma unroll
            for (int cg = 0; cg < 4; cg++) {
                int col0 = wc * 64 + cg * 16;
                wmma::load_matrix_sync(bh, Wsh + col0 * 72 + k0 * 16, 72);
                wmma::load_matrix_sync(bl, Wsl + col0 * 72 + k0 * 16, 72);
                wmma::mma_sync(acc[cg], ah, bh, acc[cg]);
                wmma::mma_sync(acc[cg], ah, bl, acc[cg]);
                wmma::mma_sync(acc[cg], al, bh, acc[cg]);
            }
        }
        __syncthreads();   // mma reads done before restaging / C store
    }
#pragma unroll
    for (int cg = 0; cg < 4; cg++)
        wmma::store_matrix_sync(Cs + wr * 16 * 136 + wc * 64 + cg * 16, acc[cg], 136,
                                wmma::mem_row_major);
    __syncthreads();

    // epilogue: fp16 h store + attention dots (4 nodes/thread)
    int og = t & 15, ng = t >> 4;
    int o0 = og * 8;
    int head = og >> 1;
    int c0 = (og & 1) * 8;
#pragma unroll
    for (int i = 0; i < 4; i++) {
        int nl = ng * 4 + i;
        int n = n0 + nl;
        float v[8];
#pragma unroll
        for (int q = 0; q < 8; q++) v[q] = Cs[nl * 136 + o0 + q];
        uint4 pack;
        pack.x = h2_to_u(__floats2half2_rn(v[0], v[1]));
        pack.y = h2_to_u(__floats2half2_rn(v[2], v[3]));
        pack.z = h2_to_u(__floats2half2_rn(v[4], v[5]));
        pack.w = h2_to_u(__floats2half2_rn(v[6], v[7]));
        *(uint4*)(g_h + n * 128 + o0) = pack;
        float pd = 0.f, ps = 0.f;
#pragma unroll
        for (int q = 0; q < 8; q++) {
            pd += v[q] * A[head * 32 + c0 + q];
            ps += v[q] * A[head * 32 + 16 + c0 + q];
        }
        pd += __shfl_xor_sync(0xffffffffu, pd, 1);
        ps += __shfl_xor_sync(0xffffffffu, ps, 1);
        if (!(og & 1)) { g_adst[n * 8 + head] = pd; g_srw[n * 8 + head].x = ps; }
    }
}

// ============ power-mean pooling (BN affine inline) + head + CSR counter re-zero ============
__global__ void k_poolsum(const float* __restrict__ pp, const float* __restrict__ gam,
                          const float* __restrict__ bet) {
    float p = pp[0];
    int b = blockIdx.y, chunk = blockIdx.x, c = threadIdx.x;  // 128 threads
    float m = g_bnsum[c] * (1.f / (float)N_NODES);
    float var = g_bnsq[c] * (1.f / (float)N_NODES) - m * m;
    float sc = gam[c] * rsqrtf(var + 1e-5f);
    float sh = bet[c] - m * sc;
    float s = 0.f;
    int i0 = chunk * 313;
    int iend = min(i0 + 313, NODE_PER_G);
    for (int i = i0; i < iend; i++) {
        float v = __half2float(g_acc[(b * NODE_PER_G + i) * 128 + c]);
        float y = v * sc + sh;
        y = (y >= 0.f) ? y : 0.2f * y;
        y = fminf(fmaxf(y, 0.f), 100.f);
        if (p != 1.f) y = (y > 0.f) ? __powf(y, p) : 0.f;
        s += y;
    }
    atomicAdd(&g_pool[b * 128 + c], s);
    // re-zero bump-CSR counters for the next graph replay
    int tid = (b * 32 + chunk) * 128 + c;
    for (int idx = tid; idx < N_NODES; idx += 32 * BATCH * 128) {
        g_cntS[idx] = 0;
        g_cntD[idx] = 0;
    }
}
__global__ void k_final(float* out, int out_size, const float* __restrict__ pp,
                        const float* __restrict__ Wg, const float* __restrict__ bg) {
    __shared__ float xg[1024];
    __shared__ float lg[16];
    int t = threadIdx.x;   // 1024
    float p = pp[0];
    {
        float m = g_pool[t] * (1.f / (float)NODE_PER_G);
        g_pool[t] = 0.f;
        if (t < 128) { g_bnsum[t] = 0.f; g_bnsq[t] = 0.f; }
        m = fminf(fmaxf(m, 0.f), 100.f);
        if (p != 1.f) m = (m > 0.f) ? __powf(m, 1.f / p) : 0.f;
        xg[t] = m;
    }
    __syncthreads();
    if (t < 16) {
        int b = t >> 1, cls = t & 1;
        float a = bg[cls];
        const float* w = Wg + cls * 128;
        const float* xr = xg + b * 128;
        for (int c2 = 0; c2 < 128; c2++) a += xr[c2] * w[c2];
        lg[t] = a;
        if (t < out_size) out[t] = a;
    }
    __syncthreads();
    if (t < 8 && (16 + t) < out_size) {
        out[16 + t] = (lg[2 * t + 1] > lg[2 * t]) ? 1.f : 0.f;
    }
}

// ============================ host driver (11 launches) ============================
extern "C" void kernel_launch(void* const* d_in, const int* in_sizes, int n_in,
                              void* d_out, int out_size) {
    const float* x    = (const float*)d_in[0];
    const int*   ei   = (const int*)d_in[1];
    const float* W1   = (const float*)d_in[2];
    const float* att1 = (const float*)d_in[3];
    const float* b1   = (const float*)d_in[4];
    const float* g1   = (const float*)d_in[5];
    const float* be1  = (const float*)d_in[6];
    const float* W2   = (const float*)d_in[7];
    const float* att2 = (const float*)d_in[8];
    const float* b2   = (const float*)d_in[9];
    const float* g2   = (const float*)d_in[10];
    const float* be2  = (const float*)d_in[11];
    const float* W3   = (const float*)d_in[12];
    const float* att3 = (const float*)d_in[13];
    const float* b3   = (const float*)d_in[14];
    const float* g3   = (const float*)d_in[15];
    const float* be3  = (const float*)d_in[16];
    const float* p    = (const float*)d_in[17];
    const float* Wg   = (const float*)d_in[18];
    const float* bg   = (const float*)d_in[19];
    float* out = (float*)d_out;

    static bool attr_set = false;
    if (!attr_set) {
        cudaFuncSetAttribute(k_gemm128, cudaFuncAttributeMaxDynamicSharedMemorySize, GEMM_SMEM);
        attr_set = true;
    }

    // 1: bump-bucket CSR + layer-1 GEMM + att dots + W2/W3 fp16 split
    k_build_gemm<<<EB + GB1 + WSB, 256>>>(ei, x, W1, att1, W2, W3);
    // layer 1
    k_srcsoft<<<2500, 256>>>();
    k_gather<<<2500, 256>>>(b1);
    // layer 2
    k_gemm128<<<N_NODES / 64, 256, GEMM_SMEM>>>(0, att2, g1, be1);   // <- profiled slot
    k_srcsoft<<<2500, 256>>>();
    k_gather<<<2500, 256>>>(b2);
    // layer 3
    k_gemm128<<<N_NODES / 64, 256, GEMM_SMEM>>>(1, att3, g2, be2);
    k_srcsoft<<<2500, 256>>>();
    k_gather<<<2500, 256>>>(b3);
    // pooling + head (+ CSR counter re-zero)
    k_poolsum<<<dim3(32, BATCH), 128>>>(p, g3, be3);
    k_final<<<1, 1024>>>(out, out_size, p, Wg, bg);
}